// round 1
// baseline (speedup 1.0000x reference)
#include <cuda_runtime.h>
#include <math.h>

#define EPS_SQ 1e-8f

// ---------------- scratch (static device arrays; no allocation) ----------------
__device__ float  d_h1[52428800];    // conv1 out [512][256][20][20]  (~210 MB)
__device__ float2 d_w2p[2949120];    // packed conv2 weights [256ci][9ky][5pair][256co]
__device__ float  d_u[4718592];      // capsule inputs u [512][1152][8]
__device__ float  d_uhat[94371840];  // u_hat [512][1152][160]        (~377 MB)

// ---------------- conv1: 1->256, 9x9, stride 1, ReLU ----------------
// block = batch b, thread = co (256). Input 28x28 in smem; weights in regs.
__global__ __launch_bounds__(256) void conv1_kernel(
    const float* __restrict__ in, const float* __restrict__ w,
    const float* __restrict__ bias)
{
    int b  = blockIdx.x;
    int co = threadIdx.x;
    __shared__ __align__(16) float si[784];
    for (int t = co; t < 784; t += 256) si[t] = in[b * 784 + t];
    __syncthreads();

    float wr[81];
#pragma unroll
    for (int k = 0; k < 81; k++) wr[k] = w[co * 81 + k];
    float bv = bias[co];

    float* outp = d_h1 + ((size_t)b * 256 + co) * 400;

    for (int oy = 0; oy < 20; oy++) {
        for (int oxp = 0; oxp < 10; oxp++) {
            int ox = oxp * 2;
            float a0 = bv, a1 = bv;
#pragma unroll
            for (int ky = 0; ky < 9; ky++) {
                const float2* r2 = (const float2*)&si[(oy + ky) * 28 + ox]; // even index -> 8B aligned
                float x[10];
#pragma unroll
                for (int u2 = 0; u2 < 5; u2++) {
                    float2 v = r2[u2];
                    x[2 * u2] = v.x; x[2 * u2 + 1] = v.y;
                }
#pragma unroll
                for (int kx = 0; kx < 9; kx++) {
                    float wv = wr[ky * 9 + kx];
                    a0 += wv * x[kx];
                    a1 += wv * x[kx + 1];
                }
            }
            outp[oy * 20 + ox]     = fmaxf(a0, 0.f);
            outp[oy * 20 + ox + 1] = fmaxf(a1, 0.f);
        }
    }
}

// ---------------- pack conv2 weights into f32x2 pairs ----------------
// dst[((ci*45 + ky*5 + t)*256 + co)] = (w[co][ci][ky][2t], t<4 ? w[co][ci][ky][2t+1] : 0)
__global__ __launch_bounds__(256) void packw2_kernel(const float* __restrict__ w2)
{
    int idx = blockIdx.x * 256 + threadIdx.x;
    if (idx >= 256 * 45 * 256) return;
    int co = idx % 256;
    int r  = idx / 256;
    int ci = r / 45;
    int s  = r % 45;
    int ky = s / 5, t = s % 5;
    const float* src = w2 + ((size_t)(co * 256 + ci) * 81) + ky * 9 + 2 * t;
    float lo = src[0];
    float hi = (t < 4) ? src[1] : 0.f;
    d_w2p[idx] = make_float2(lo, hi);
}

// ---------------- conv2: 256->256, 9x9, stride 2, writes transposed u layout ----
// block = batch b, thread = co. 36 f32x2 accumulators (kx even/odd split).
__global__ __launch_bounds__(256) void conv2_kernel(const float* __restrict__ b2)
{
    int b  = blockIdx.x;
    int co = threadIdx.x;

    unsigned long long acc[36];
    {
        union { float2 f; unsigned long long u; } bi;
        bi.f = make_float2(b2[co], 0.f);
#pragma unroll
        for (int p = 0; p < 36; p++) acc[p] = bi.u;
    }

    __shared__ __align__(16) float sx[8 * 400];
    const float* xin = d_h1 + (size_t)b * 256 * 400;

    for (int cc = 0; cc < 32; cc++) {
        __syncthreads();
        for (int t = threadIdx.x; t < 3200; t += 256)
            sx[t] = xin[cc * 3200 + t];
        __syncthreads();

        for (int cl = 0; cl < 8; cl++) {
            int ci = cc * 8 + cl;
            const unsigned long long* wp =
                reinterpret_cast<const unsigned long long*>(d_w2p) + ((size_t)ci * 45) * 256 + co;
            for (int ky = 0; ky < 9; ky++) {
                const float* srow = &sx[cl * 400 + ky * 20];
#pragma unroll
                for (int t = 0; t < 5; t++) {
                    unsigned long long wll = wp[(ky * 5 + t) * 256];   // LDG.64, coalesced
#pragma unroll
                    for (int oy = 0; oy < 6; oy++) {
#pragma unroll
                        for (int ox = 0; ox < 6; ox++) {
                            // even index -> 8B aligned LDS.64
                            unsigned long long xll =
                                *reinterpret_cast<const unsigned long long*>(
                                    &srow[oy * 40 + ox * 2 + 2 * t]);
                            asm("fma.rn.f32x2 %0, %1, %2, %0;"
                                : "+l"(acc[oy * 6 + ox]) : "l"(xll), "l"(wll));
                        }
                    }
                }
            }
        }
    }

    // write u[b][i][p] with i*8+p = ox*1536 + oy*256 + co (torch transpose+view)
    float* uo = d_u + (size_t)b * 9216;
#pragma unroll
    for (int oy = 0; oy < 6; oy++) {
#pragma unroll
        for (int ox = 0; ox < 6; ox++) {
            union { float2 f; unsigned long long u; } r;
            r.u = acc[oy * 6 + ox];
            uo[ox * 1536 + oy * 256 + co] = r.f.x + r.f.y;
        }
    }
}

// ---------------- u_hat + dynamic routing, fused per batch ----------------
// block = batch b, 320 threads (10 warps). Dynamic smem: b_ij + c + reduction bufs.
__global__ __launch_bounds__(320) void caps_kernel(
    const float* __restrict__ capW, float* __restrict__ outp)
{
    extern __shared__ float smem[];
    float* bs   = smem;            // [1152*10]
    float* cs   = bs + 11520;      // [1152*10]
    float* red  = cs + 11520;      // [320]
    float* sv   = red + 320;       // [160]
    float* coef = sv + 160;        // [16]

    int tid  = threadIdx.x;
    int b    = blockIdx.x;
    int lane = tid & 31, warp = tid >> 5;

    // init b_ij = 0
    for (int t = tid; t < 11520; t += 320) bs[t] = 0.f;

    // ---- Phase A: u_hat[b][i][jq] = sum_p u[b][i][p] * W[i][j][p][q] ----
    float* ub = d_uhat + (size_t)b * 184320;
    int offr[5];
#pragma unroll
    for (int r = 0; r < 5; r++) {
        int jq = lane + 32 * r;
        offr[r] = (jq >> 4) * 128 + (jq & 15);
    }
    for (int i = warp; i < 1152; i += 10) {
        const float* uptr = d_u + (size_t)b * 9216 + i * 8;
        float up[8];
#pragma unroll
        for (int p = 0; p < 8; p++) up[p] = uptr[p];
        const float* Wb = capW + (size_t)i * 1280;
        float a[5] = {0.f, 0.f, 0.f, 0.f, 0.f};
#pragma unroll
        for (int p = 0; p < 8; p++) {
#pragma unroll
            for (int r = 0; r < 5; r++)
                a[r] += up[p] * Wb[offr[r] + p * 16];
        }
        float* uo = ub + (size_t)i * 160;
#pragma unroll
        for (int r = 0; r < 5; r++) uo[lane + 32 * r] = a[r];
    }
    __syncthreads();

    // ---- Phase B: 3 routing iterations ----
    for (int iter = 0; iter < 3; iter++) {
        // c = softmax_j(b)
        for (int i = tid; i < 1152; i += 320) {
            float m = -1e30f;
#pragma unroll
            for (int j = 0; j < 10; j++) m = fmaxf(m, bs[i * 10 + j]);
            float e[10], se = 0.f;
#pragma unroll
            for (int j = 0; j < 10; j++) { e[j] = __expf(bs[i * 10 + j] - m); se += e[j]; }
            float inv = 1.f / se;
#pragma unroll
            for (int j = 0; j < 10; j++) cs[i * 10 + j] = e[j] * inv;
        }
        __syncthreads();

        // s[j][q] = sum_i c[i][j] * uhat[i][j][q]   (two i-halves in parallel)
        {
            int jq = tid % 160, g = tid / 160;
            int j  = jq >> 4;
            float acc = 0.f;
            int i0 = g * 576, i1 = i0 + 576;
#pragma unroll 4
            for (int i = i0; i < i1; i++)
                acc += cs[i * 10 + j] * ub[(size_t)i * 160 + jq];
            red[tid] = acc;
        }
        __syncthreads();
        if (tid < 160) sv[tid] = red[tid] + red[tid + 160];
        __syncthreads();
        if (tid < 10) {
            float sq = 0.f;
#pragma unroll
            for (int q = 0; q < 16; q++) { float v = sv[tid * 16 + q]; sq += v * v; }
            coef[tid] = sq * rsqrtf(sq + EPS_SQ) / (1.f + sq);
        }
        __syncthreads();
        if (tid < 160) {
            float v = coef[tid >> 4] * sv[tid];
            sv[tid] = v;
            if (iter == 2) outp[b * 160 + tid] = v;
        }
        __syncthreads();

        if (iter < 2) {
            // b[i][j] += sum_q uhat[i][j][q] * v[j][q]
            for (int idx = tid; idx < 11520; idx += 320) {
                int i = idx / 10, j = idx % 10;
                const float4* uhr = (const float4*)(ub + (size_t)i * 160 + j * 16);
                const float4* vv  = (const float4*)(sv + j * 16);
                float dot = 0.f;
#pragma unroll
                for (int k4 = 0; k4 < 4; k4++) {
                    float4 a = uhr[k4], c4 = vv[k4];
                    dot += a.x * c4.x + a.y * c4.y + a.z * c4.z + a.w * c4.w;
                }
                bs[idx] += dot;
            }
            __syncthreads();
        }
    }
}

// ---------------- launch ----------------
extern "C" void kernel_launch(void* const* d_in, const int* in_sizes, int n_in,
                              void* d_out, int out_size)
{
    const float* inp = (const float*)d_in[0];
    const float* w1  = (const float*)d_in[1];
    const float* b1  = (const float*)d_in[2];
    const float* w2  = (const float*)d_in[3];
    const float* b2  = (const float*)d_in[4];
    const float* cw  = (const float*)d_in[5];
    float* outp = (float*)d_out;

    conv1_kernel<<<512, 256>>>(inp, w1, b1);
    packw2_kernel<<<(256 * 45 * 256 + 255) / 256, 256>>>(w2);
    conv2_kernel<<<512, 256>>>(b2);

    const int caps_smem = (11520 + 11520 + 320 + 160 + 16) * 4; // 94144 B
    cudaFuncSetAttribute(caps_kernel, cudaFuncAttributeMaxDynamicSharedMemorySize, caps_smem);
    caps_kernel<<<512, 320, caps_smem>>>(cw, outp);
}